// round 11
// baseline (speedup 1.0000x reference)
#include <cuda_runtime.h>
#include <cuda_bf16.h>
#include <math.h>
#include <stdint.h>

#define SEQ 128
#define BATCH 32
#define NHID 512
#define NVOC 32000
#define M_ROWS (SEQ * BATCH)                 /* 4096 */
#define HID_OFF ((size_t)M_ROWS * NVOC)      /* 131072000 */
#define LSTM_GRID 128

// ------------------------- device scratch (no allocs allowed) ----------------
__device__ float g_g0xT[(size_t)4 * NHID * M_ROWS];   // layer0 x-gates^T [2048][4096]
__device__ float g_h0[2][BATCH * NHID];
__device__ float g_h1[2][BATCH * NHID];
__device__ unsigned g_count = 0;
__device__ unsigned g_epoch = 0;

// split-bf16 operands
__device__ __nv_bfloat16 g_Ehi[(size_t)M_ROWS * NHID];   // emb  [m][k]
__device__ __nv_bfloat16 g_Elo[(size_t)M_ROWS * NHID];
__device__ __nv_bfloat16 g_W0hi[(size_t)2048 * NHID];    // fcW0 x-part [n][k]
__device__ __nv_bfloat16 g_W0lo[(size_t)2048 * NHID];
__device__ __nv_bfloat16 g_Ahi[(size_t)M_ROWS * NHID];   // h1 out [m][k]
__device__ __nv_bfloat16 g_Alo[(size_t)M_ROWS * NHID];
__device__ __nv_bfloat16 g_Bhi[(size_t)NVOC * NHID];     // decW  [n][k]
__device__ __nv_bfloat16 g_Blo[(size_t)NVOC * NHID];

// ------------------------- shared PTX helpers --------------------------------
__device__ __forceinline__ uint32_t smem_u32(const void* p) {
  uint32_t a;
  asm("{ .reg .u64 t; cvta.to.shared.u64 t, %1; cvt.u32.u64 %0, t; }"
      : "=r"(a) : "l"(p));
  return a;
}
__device__ __forceinline__ void cp16(uint32_t dst, const void* src) {
  asm volatile("cp.async.cg.shared.global [%0], [%1], 16;\n" ::"r"(dst), "l"(src));
}
__device__ __forceinline__ void ldm_x4(uint32_t a, uint32_t* r) {
  asm volatile("ldmatrix.sync.aligned.m8n8.x4.shared.b16 {%0,%1,%2,%3}, [%4];"
               : "=r"(r[0]), "=r"(r[1]), "=r"(r[2]), "=r"(r[3]) : "r"(a));
}
__device__ __forceinline__ void ldm_x2(uint32_t a, uint32_t* r) {
  asm volatile("ldmatrix.sync.aligned.m8n8.x2.shared.b16 {%0,%1}, [%2];"
               : "=r"(r[0]), "=r"(r[1]) : "r"(a));
}
__device__ __forceinline__ void mma16816(float* c, const uint32_t* a,
                                         const uint32_t* b) {
  asm volatile(
      "mma.sync.aligned.m16n8k16.row.col.f32.bf16.bf16.f32 "
      "{%0,%1,%2,%3}, {%4,%5,%6,%7}, {%8,%9}, {%0,%1,%2,%3};"
      : "+f"(c[0]), "+f"(c[1]), "+f"(c[2]), "+f"(c[3])
      : "r"(a[0]), "r"(a[1]), "r"(a[2]), "r"(a[3]), "r"(b[0]), "r"(b[1]));
}

// ------------------------- embedding gather (split bf16, row-major) ----------
__global__ void embed_kernel(const int* __restrict__ tok,
                             const float* __restrict__ embW) {
  int idx = blockIdx.x * 256 + threadIdx.x;
  if (idx >= M_ROWS * NHID) return;
  int m = idx >> 9;
  int k = idx & 511;
  float v = embW[(size_t)tok[m] * NHID + k];
  __nv_bfloat16 h = __float2bfloat16(v);
  g_Ehi[idx] = h;
  g_Elo[idx] = __float2bfloat16(v - __bfloat162float(h));
}

// ------------------------- weight split conversions --------------------------
__global__ void convW0_kernel(const float* __restrict__ fcW) {
  int i = blockIdx.x * 256 + threadIdx.x;
  if (i >= 2048 * NHID) return;
  int n = i >> 9, k = i & 511;
  float x = fcW[(size_t)n * 1024 + k];
  __nv_bfloat16 h = __float2bfloat16(x);
  g_W0hi[i] = h;
  g_W0lo[i] = __float2bfloat16(x - __bfloat162float(h));
}

__global__ void convB_kernel(const float* __restrict__ W) {
  int i = blockIdx.x * 256 + threadIdx.x;
  if (i >= NVOC * NHID) return;
  float x = W[i];
  __nv_bfloat16 h = __float2bfloat16(x);
  g_Bhi[i] = h;
  g_Blo[i] = __float2bfloat16(x - __bfloat162float(h));
}

// ------------------------- HMMA GEMM (decoder + gemm0) -----------------------
// C = A(split) . B(split)^T + bias ; 3-term split-bf16, K=512.
// Tile 128x128, 8 warps (2x4), warp 64x32, BK=32, 3-stage cp.async, 2 CTA/SM.
// SMEM row (128B, SW128 swizz): [ hi k0..31 | lo k0..31 ] per matrix row.
#define STG 32768                       /* per-stage bytes: A 16K + B 16K */
#define SO_BUF 1024
#define DEC_SMEM (1024 + 3 * STG)       /* 99328 */

__device__ __forceinline__ void dec_load(uint32_t sb, int s, int kt,
                                         int m0, int n0, int tid,
                                         const __nv_bfloat16* Ahi,
                                         const __nv_bfloat16* Alo,
                                         const __nv_bfloat16* Bhi,
                                         const __nv_bfloat16* Blo) {
  const int k0 = kt * 32;
  const uint32_t base = sb + SO_BUF + (uint32_t)s * STG;
#pragma unroll
  for (int i = tid; i < 1024; i += 256) {
    int row = i >> 3, c = i & 7;
    uint32_t phys = base + row * 128 + ((c ^ (row & 7)) << 4);
    size_t goff = (size_t)k0 + (c & 3) * 8;
    const __nv_bfloat16* asrc =
        (c < 4 ? Ahi : Alo) + (size_t)(m0 + row) * NHID + goff;
    cp16(phys, asrc);
    const __nv_bfloat16* bsrc =
        (c < 4 ? Bhi : Blo) + (size_t)(n0 + row) * NHID + goff;
    cp16(phys + 16384, bsrc);
  }
  asm volatile("cp.async.commit_group;\n" ::: "memory");
}

template <bool TRANSC>
__global__ void __launch_bounds__(256, 2)
mma_gemm(const __nv_bfloat16* __restrict__ Ahi,
         const __nv_bfloat16* __restrict__ Alo,
         const __nv_bfloat16* __restrict__ Bhi,
         const __nv_bfloat16* __restrict__ Blo,
         const float* __restrict__ bias, float* __restrict__ C, int ldc) {
  extern __shared__ char smem[];
  uint32_t sb = smem_u32(smem);
  const int tid = threadIdx.x;
  const int wid = tid >> 5;
  const int lane = tid & 31;
  const int m0 = blockIdx.x * 128;
  const int n0 = blockIdx.y * 128;
  const int wm = (wid >> 2) * 64;
  const int wn = (wid & 3) * 32;

  if (tid < 128) ((float*)smem)[tid] = bias[n0 + tid];

  float acc[4][4][4];
#pragma unroll
  for (int i = 0; i < 4; i++)
#pragma unroll
    for (int j = 0; j < 4; j++)
#pragma unroll
      for (int v = 0; v < 4; v++) acc[i][j][v] = 0.f;

  dec_load(sb, 0, 0, m0, n0, tid, Ahi, Alo, Bhi, Blo);
  dec_load(sb, 1, 1, m0, n0, tid, Ahi, Alo, Bhi, Blo);

  // per-lane fragment coordinates (logical; swizzle applied per-address)
  const int arow = lane & 15;            // A: x4 uses 16 rows
  const int ahalf = lane >> 4;           // A: which 16B half of k16 window
  const int aswz = arow & 7;
  const int brow4 = lane & 7;            // B x4: 8 rows per 8x8 matrix
  const int bgrp = lane >> 3;            // 0..3 matrix group
  const int brow_off = (bgrp >> 1) * 8;  // +0 / +8 rows (nf parity in pair)
  const int bkhalf = bgrp & 1;           // k 16B half

  int s_cur = 0, s_nxt = 2;              // stage of kt, stage of kt+2
#pragma unroll 1
  for (int kt = 0; kt < 16; ++kt) {
    if (kt == 15)
      asm volatile("cp.async.wait_group 0;\n" ::: "memory");
    else
      asm volatile("cp.async.wait_group 1;\n" ::: "memory");
    __syncthreads();

    if (kt + 2 < 16)
      dec_load(sb, s_nxt, kt + 2, m0, n0, tid, Ahi, Alo, Bhi, Blo);

    const uint32_t abase = sb + SO_BUF + (uint32_t)s_cur * STG;
    const uint32_t bbase = abase + 16384;

#pragma unroll
    for (int ks = 0; ks < 2; ++ks) {
      uint32_t ah[4][4], al[4][4];
      const int achunk = (ks * 2 + ahalf) ^ aswz;   // swizzled 16B chunk
#pragma unroll
      for (int mf = 0; mf < 4; ++mf) {
        uint32_t addr = abase + (uint32_t)(wm + mf * 16 + arow) * 128 +
                        (achunk << 4);
        ldm_x4(addr, ah[mf]);
        ldm_x4(addr ^ 64, al[mf]);                  // lo half: chunk+4
      }
      const int bchunk = (ks * 2 + bkhalf) ^ brow4;
#pragma unroll
      for (int nfp = 0; nfp < 2; ++nfp) {
        uint32_t bh[4], bl[4];
        uint32_t addr = bbase +
                        (uint32_t)(wn + nfp * 16 + brow_off + brow4) * 128 +
                        (bchunk << 4);
        ldm_x4(addr, bh);                           // nf=2nfp (r0,r1), 2nfp+1 (r2,r3)
        ldm_x4(addr ^ 64, bl);
        const int ne = nfp * 2, no = nfp * 2 + 1;
        // product-major: acc reuse distance = 8 mma
#pragma unroll
        for (int mf = 0; mf < 4; ++mf) {
          mma16816(acc[mf][ne], ah[mf], bh);
          mma16816(acc[mf][no], ah[mf], bh + 2);
        }
#pragma unroll
        for (int mf = 0; mf < 4; ++mf) {
          mma16816(acc[mf][ne], ah[mf], bl);
          mma16816(acc[mf][no], ah[mf], bl + 2);
        }
#pragma unroll
        for (int mf = 0; mf < 4; ++mf) {
          mma16816(acc[mf][ne], al[mf], bh);
          mma16816(acc[mf][no], al[mf], bh + 2);
        }
      }
    }
    s_cur = s_cur == 2 ? 0 : s_cur + 1;
    s_nxt = s_nxt == 2 ? 0 : s_nxt + 1;
  }

  const float* bsm = (const float*)smem;
  const int rl = lane >> 2, cl = (lane & 3) * 2;
  if (!TRANSC) {
#pragma unroll
    for (int mf = 0; mf < 4; ++mf) {
      int r = m0 + wm + mf * 16 + rl;
#pragma unroll
      for (int nf = 0; nf < 4; ++nf) {
        int ci = wn + nf * 8 + cl;
        float b0 = bsm[ci], b1 = bsm[ci + 1];
        float2 v0 = make_float2(acc[mf][nf][0] + b0, acc[mf][nf][1] + b1);
        float2 v1 = make_float2(acc[mf][nf][2] + b0, acc[mf][nf][3] + b1);
        *(float2*)(C + (size_t)r * ldc + n0 + ci) = v0;
        *(float2*)(C + (size_t)(r + 8) * ldc + n0 + ci) = v1;
      }
    }
  } else {
#pragma unroll
    for (int mf = 0; mf < 4; ++mf) {
      int r = m0 + wm + mf * 16 + rl;
#pragma unroll
      for (int nf = 0; nf < 4; ++nf) {
        int ci = wn + nf * 8 + cl;
        float b0 = bsm[ci], b1 = bsm[ci + 1];
        C[(size_t)(n0 + ci) * ldc + r] = acc[mf][nf][0] + b0;
        C[(size_t)(n0 + ci + 1) * ldc + r] = acc[mf][nf][1] + b1;
        C[(size_t)(n0 + ci) * ldc + r + 8] = acc[mf][nf][2] + b0;
        C[(size_t)(n0 + ci + 1) * ldc + r + 8] = acc[mf][nf][3] + b1;
      }
    }
  }
}

// ------------------------- HMMA persistent LSTM ------------------------------
#define LW0 520
#define LW1 1032
#define LH  520
#define SO_W0HI 0
#define SO_W0LO 16640
#define SO_W1HI 33280
#define SO_W1LO 66304
#define SO_HHI  99328
#define SO_HLO  132608
#define SO_PS   165888
#define SO_ASM  198656
#define SO_B1S  202752
#define LSTM_SMEM 202816

__device__ __forceinline__ void gridbar() {
  __threadfence();
  __syncthreads();
  if (threadIdx.x == 0) {
    unsigned e = *(volatile unsigned*)&g_epoch;
    __threadfence();
    unsigned prev = atomicAdd(&g_count, 1u);
    if (prev == (unsigned)(LSTM_GRID - 1)) {
      atomicExch(&g_count, 0u);
      __threadfence();
      atomicAdd(&g_epoch, 1u);
    } else {
      while (*(volatile unsigned*)&g_epoch == e) __nanosleep(64);
    }
    __threadfence();
  }
  __syncthreads();
}

__device__ __forceinline__ void stage_split(char* smem, const float* __restrict__ src) {
  __nv_bfloat16* Hhi = (__nv_bfloat16*)(smem + SO_HHI);
  __nv_bfloat16* Hlo = (__nv_bfloat16*)(smem + SO_HLO);
  for (int i = threadIdx.x; i < 4096; i += 256) {
    int b = i >> 7;
    int k4 = (i & 127) << 2;
    float4 v = *(const float4*)(src + b * 512 + k4);
    __nv_bfloat162 h0, h1, l0, l1;
    h0.x = __float2bfloat16(v.x); l0.x = __float2bfloat16(v.x - __bfloat162float(h0.x));
    h0.y = __float2bfloat16(v.y); l0.y = __float2bfloat16(v.y - __bfloat162float(h0.y));
    h1.x = __float2bfloat16(v.z); l1.x = __float2bfloat16(v.z - __bfloat162float(h1.x));
    h1.y = __float2bfloat16(v.w); l1.y = __float2bfloat16(v.w - __bfloat162float(h1.y));
    *(__nv_bfloat162*)(Hhi + b * LH + k4) = h0;
    *(__nv_bfloat162*)(Hhi + b * LH + k4 + 2) = h1;
    *(__nv_bfloat162*)(Hlo + b * LH + k4) = l0;
    *(__nv_bfloat162*)(Hlo + b * LH + k4 + 2) = l1;
  }
}

__device__ __forceinline__ float sigm(float x) { return 1.f / (1.f + __expf(-x)); }

__global__ void __launch_bounds__(256, 1)
lstm_kernel(const float* __restrict__ fcW, const float* __restrict__ fcb,
            float* __restrict__ out) {
  extern __shared__ char smem[];
  uint32_t sb = smem_u32(smem);
  __nv_bfloat16* W0hi = (__nv_bfloat16*)(smem + SO_W0HI);
  __nv_bfloat16* W0lo = (__nv_bfloat16*)(smem + SO_W0LO);
  __nv_bfloat16* W1hi = (__nv_bfloat16*)(smem + SO_W1HI);
  __nv_bfloat16* W1lo = (__nv_bfloat16*)(smem + SO_W1LO);
  float* ps = (float*)(smem + SO_PS);
  float* a_sm = (float*)(smem + SO_ASM);
  float* b1s = (float*)(smem + SO_B1S);

  const int tid = threadIdx.x;
  const int w = tid >> 5;
  const int lane = tid & 31;
  const int cta = blockIdx.x;

  for (int i = tid; i < 16 * 512; i += 256) {
    int r = i >> 9, k = i & 511;
    int gr = cta * 4 + (r >> 2) + (r & 3) * 512;
    float v = fcW[(size_t)gr * 1024 + 512 + k];
    __nv_bfloat16 h = __float2bfloat16(v);
    W0hi[r * LW0 + k] = h;
    W0lo[r * LW0 + k] = __float2bfloat16(v - __bfloat162float(h));
  }
  for (int i = tid; i < 16 * 1024; i += 256) {
    int r = i >> 10, k = i & 1023;
    int gr = cta * 4 + (r >> 2) + (r & 3) * 512;
    float v = fcW[(size_t)2048 * 1024 + (size_t)gr * 1024 + k];
    __nv_bfloat16 h = __float2bfloat16(v);
    W1hi[r * LW1 + k] = h;
    W1lo[r * LW1 + k] = __float2bfloat16(v - __bfloat162float(h));
  }
  if (tid < 16)
    b1s[tid] = fcb[2048 + cta * 4 + (tid >> 2) + (tid & 3) * 512];

  {
    int g = cta * 256 + tid;
    if (g < BATCH * NHID) {
      g_h0[0][g] = 0.f; g_h0[1][g] = 0.f;
      g_h1[0][g] = 0.f; g_h1[1][g] = 0.f;
    }
  }
  gridbar();

  float c0r = 0.f, c1r = 0.f;
  const int U = cta * 4 + (w & 3);
  float* hid = out + HID_OFF;

  const int arow = lane & 15, achk = (lane >> 4) * 8;
  const int brow = lane & 7, bchk = ((lane >> 3) & 1) * 8;
  const int rl = lane >> 2, cl = (lane & 3) * 2;

#pragma unroll 1
  for (int p = 0; p <= SEQ; ++p) {
    const int wp = p & 1;

    float xg[4] = {0.f, 0.f, 0.f, 0.f};
    if (w < 4 && p < SEQ) {
#pragma unroll
      for (int g = 0; g < 4; ++g)
        xg[g] = g_g0xT[(size_t)(U + g * 512) * M_ROWS + p * 32 + lane];
    }

    float acc0[2][2][4], acc1[2][2][4];
#pragma unroll
    for (int i = 0; i < 2; i++)
#pragma unroll
      for (int j = 0; j < 2; j++)
#pragma unroll
        for (int v = 0; v < 4; v++) { acc0[i][j][v] = 0.f; acc1[i][j][v] = 0.f; }

    stage_split(smem, &g_h0[wp ^ 1][0]);
    __syncthreads();
#pragma unroll
    for (int kt = 0; kt < 4; ++kt) {
      const int kk = (w * 4 + kt) * 16;
      uint32_t ah[2][4], al[2][4], b0h[2][2], b0l[2][2], b1h[2][2], b1l[2][2];
#pragma unroll
      for (int mf = 0; mf < 2; ++mf) {
        uint32_t off = (uint32_t)((mf * 16 + arow) * LH + kk + achk) * 2;
        ldm_x4(sb + SO_HHI + off, ah[mf]);
        ldm_x4(sb + SO_HLO + off, al[mf]);
      }
#pragma unroll
      for (int nf = 0; nf < 2; ++nf) {
        uint32_t o0 = (uint32_t)((nf * 8 + brow) * LW0 + kk + bchk) * 2;
        ldm_x2(sb + SO_W0HI + o0, b0h[nf]);
        ldm_x2(sb + SO_W0LO + o0, b0l[nf]);
        uint32_t o1 = (uint32_t)((nf * 8 + brow) * LW1 + kk + bchk) * 2;
        ldm_x2(sb + SO_W1HI + o1, b1h[nf]);
        ldm_x2(sb + SO_W1LO + o1, b1l[nf]);
      }
      // product-major ordering: acc reuse distance = 8
#pragma unroll
      for (int mf = 0; mf < 2; ++mf)
#pragma unroll
        for (int nf = 0; nf < 2; ++nf) {
          mma16816(acc0[mf][nf], ah[mf], b0h[nf]);
          mma16816(acc1[mf][nf], ah[mf], b1h[nf]);
        }
#pragma unroll
      for (int mf = 0; mf < 2; ++mf)
#pragma unroll
        for (int nf = 0; nf < 2; ++nf) {
          mma16816(acc0[mf][nf], ah[mf], b0l[nf]);
          mma16816(acc1[mf][nf], ah[mf], b1l[nf]);
        }
#pragma unroll
      for (int mf = 0; mf < 2; ++mf)
#pragma unroll
        for (int nf = 0; nf < 2; ++nf) {
          mma16816(acc0[mf][nf], al[mf], b0h[nf]);
          mma16816(acc1[mf][nf], al[mf], b1h[nf]);
        }
    }
    __syncthreads();

    stage_split(smem, &g_h1[wp ^ 1][0]);
    __syncthreads();
#pragma unroll
    for (int kt = 0; kt < 4; ++kt) {
      const int kk = (w * 4 + kt) * 16;
      uint32_t ah[2][4], al[2][4], b1h[2][2], b1l[2][2];
#pragma unroll
      for (int mf = 0; mf < 2; ++mf) {
        uint32_t off = (uint32_t)((mf * 16 + arow) * LH + kk + achk) * 2;
        ldm_x4(sb + SO_HHI + off, ah[mf]);
        ldm_x4(sb + SO_HLO + off, al[mf]);
      }
#pragma unroll
      for (int nf = 0; nf < 2; ++nf) {
        uint32_t o1 = (uint32_t)((nf * 8 + brow) * LW1 + 512 + kk + bchk) * 2;
        ldm_x2(sb + SO_W1HI + o1, b1h[nf]);
        ldm_x2(sb + SO_W1LO + o1, b1l[nf]);
      }
#pragma unroll
      for (int mf = 0; mf < 2; ++mf)
#pragma unroll
        for (int nf = 0; nf < 2; ++nf) mma16816(acc1[mf][nf], ah[mf], b1h[nf]);
#pragma unroll
      for (int mf = 0; mf < 2; ++mf)
#pragma unroll
        for (int nf = 0; nf < 2; ++nf) mma16816(acc1[mf][nf], ah[mf], b1l[nf]);
#pragma unroll
      for (int mf = 0; mf < 2; ++mf)
#pragma unroll
        for (int nf = 0; nf < 2; ++nf) mma16816(acc1[mf][nf], al[mf], b1h[nf]);
    }

#pragma unroll
    for (int mf = 0; mf < 2; ++mf)
#pragma unroll
      for (int nf = 0; nf < 2; ++nf)
#pragma unroll
        for (int v = 0; v < 4; ++v) {
          int b = mf * 16 + rl + ((v & 2) ? 8 : 0);
          int n = nf * 8 + cl + (v & 1);
          ps[(w * 32 + n) * 32 + b] = acc0[mf][nf][v];
          ps[(w * 32 + 16 + n) * 32 + b] = acc1[mf][nf][v];
        }
    __syncthreads();

#pragma unroll
    for (int q = 0; q < 4; ++q) {
      int o = tid + q * 256;
      int n = o >> 5, b = o & 31;
      float s = 0.f;
#pragma unroll
      for (int ww = 0; ww < 8; ++ww) s += ps[(ww * 32 + n) * 32 + b];
      a_sm[n * 32 + b] = s;
    }
    __syncthreads();

    if (w < 4) {
      if (p < SEQ) {
        float a[4];
#pragma unroll
        for (int g = 0; g < 4; ++g)
          a[g] = a_sm[(w * 4 + g) * 32 + lane] + xg[g];
        float ig = sigm(a[0]), fg = sigm(a[1]), og = sigm(a[2]);
        float bg = tanhf(a[3]);
        c0r = fg * c0r + ig * bg;
        float h0v = og * tanhf(c0r);
        g_h0[wp][lane * 512 + U] = h0v;
        if (p == SEQ - 1) hid[lane * 512 + U] = h0v;
      }
    } else {
      if (p >= 1) {
        float a[4];
#pragma unroll
        for (int g = 0; g < 4; ++g)
          a[g] = a_sm[(16 + (w - 4) * 4 + g) * 32 + lane] + b1s[(w - 4) * 4 + g];
        float ig = sigm(a[0]), fg = sigm(a[1]), og = sigm(a[2]);
        float bg = tanhf(a[3]);
        c1r = fg * c1r + ig * bg;
        float h1v = og * tanhf(c1r);
        g_h1[wp][lane * 512 + U] = h1v;
        // fused convA: write split-bf16 decoder A operand directly
        {
          size_t o = (size_t)((p - 1) * 32 + lane) * NHID + U;
          __nv_bfloat16 hh = __float2bfloat16(h1v);
          g_Ahi[o] = hh;
          g_Alo[o] = __float2bfloat16(h1v - __bfloat162float(hh));
        }
        if (p == SEQ) hid[16384 + lane * 512 + U] = h1v;
      }
    }
    gridbar();
  }
}

// ------------------------- launch ------------------------------------------
extern "C" void kernel_launch(void* const* d_in, const int* in_sizes, int n_in,
                              void* d_out, int out_size) {
  const int* tok = (const int*)d_in[0];
  const float* embW = (const float*)d_in[1];
  const float* fcW = (const float*)d_in[2];
  const float* fcb = (const float*)d_in[3];
  const float* decW = (const float*)d_in[4];
  const float* decb = (const float*)d_in[5];
  float* out = (float*)d_out;

  void *p_g0xT = 0, *p_Ehi = 0, *p_Elo = 0, *p_W0hi = 0, *p_W0lo = 0;
  void *p_Ahi = 0, *p_Alo = 0, *p_Bhi = 0, *p_Blo = 0;
  cudaGetSymbolAddress(&p_g0xT, g_g0xT);
  cudaGetSymbolAddress(&p_Ehi, g_Ehi);
  cudaGetSymbolAddress(&p_Elo, g_Elo);
  cudaGetSymbolAddress(&p_W0hi, g_W0hi);
  cudaGetSymbolAddress(&p_W0lo, g_W0lo);
  cudaGetSymbolAddress(&p_Ahi, g_Ahi);
  cudaGetSymbolAddress(&p_Alo, g_Alo);
  cudaGetSymbolAddress(&p_Bhi, g_Bhi);
  cudaGetSymbolAddress(&p_Blo, g_Blo);

  cudaFuncSetAttribute(mma_gemm<false>,
                       cudaFuncAttributeMaxDynamicSharedMemorySize, DEC_SMEM);
  cudaFuncSetAttribute(mma_gemm<true>,
                       cudaFuncAttributeMaxDynamicSharedMemorySize, DEC_SMEM);
  cudaFuncSetAttribute(lstm_kernel,
                       cudaFuncAttributeMaxDynamicSharedMemorySize, LSTM_SMEM);

  // 1) embedding gather -> split bf16 row-major
  embed_kernel<<<(M_ROWS * NHID + 255) / 256, 256>>>(tok, embW);

  // 2) weight splits
  convW0_kernel<<<(2048 * NHID + 255) / 256, 256>>>(fcW);
  convB_kernel<<<(NVOC * NHID + 255) / 256, 256>>>(decW);

  // 3) layer-0 input projection (HMMA): g0xT[n][m] = emb . W0^T + b0
  mma_gemm<true><<<dim3(M_ROWS / 128, 2048 / 128), 256, DEC_SMEM>>>(
      (const __nv_bfloat16*)p_Ehi, (const __nv_bfloat16*)p_Elo,
      (const __nv_bfloat16*)p_W0hi, (const __nv_bfloat16*)p_W0lo,
      fcb, (float*)p_g0xT, M_ROWS);

  // 4) persistent HMMA LSTM recurrence (writes split-bf16 A directly)
  lstm_kernel<<<LSTM_GRID, 256, LSTM_SMEM>>>(fcW, fcb, out);

  // 5) HMMA decoder GEMM
  mma_gemm<false><<<dim3(M_ROWS / 128, NVOC / 128), 256, DEC_SMEM>>>(
      (const __nv_bfloat16*)p_Ahi, (const __nv_bfloat16*)p_Alo,
      (const __nv_bfloat16*)p_Bhi, (const __nv_bfloat16*)p_Blo,
      decb, out, NVOC);
}

// round 12
// speedup vs baseline: 1.1990x; 1.1990x over previous
#include <cuda_runtime.h>
#include <cuda_bf16.h>
#include <math.h>
#include <stdint.h>

#define SEQ 128
#define BATCH 32
#define NHID 512
#define NVOC 32000
#define M_ROWS (SEQ * BATCH)                 /* 4096 */
#define HID_OFF ((size_t)M_ROWS * NVOC)      /* 131072000 */
#define LSTM_GRID 128

// ------------------------- device scratch (no allocs allowed) ----------------
__device__ float g_g0xT[(size_t)4 * NHID * M_ROWS];   // layer0 x-gates^T [2048][4096]
__device__ unsigned g_count = 0;
__device__ unsigned g_epoch = 0;

// hidden state, split-bf16, 128B-block layout: [b][kblk][hi 64B | lo 64B]
__device__ unsigned char g_H0s[2][BATCH * 2048];
__device__ unsigned char g_H1s[2][BATCH * 2048];

// split-bf16 operands
__device__ __nv_bfloat16 g_Ehi[(size_t)M_ROWS * NHID];   // emb  [m][k]
__device__ __nv_bfloat16 g_Elo[(size_t)M_ROWS * NHID];
__device__ __nv_bfloat16 g_W0hi[(size_t)2048 * NHID];    // fcW0 x-part [n][k]
__device__ __nv_bfloat16 g_W0lo[(size_t)2048 * NHID];
__device__ __nv_bfloat16 g_Ahi[(size_t)M_ROWS * NHID];   // h1 out [m][k]
__device__ __nv_bfloat16 g_Alo[(size_t)M_ROWS * NHID];
__device__ __nv_bfloat16 g_Bhi[(size_t)NVOC * NHID];     // decW  [n][k]
__device__ __nv_bfloat16 g_Blo[(size_t)NVOC * NHID];

// ------------------------- shared PTX helpers --------------------------------
__device__ __forceinline__ uint32_t smem_u32(const void* p) {
  uint32_t a;
  asm("{ .reg .u64 t; cvta.to.shared.u64 t, %1; cvt.u32.u64 %0, t; }"
      : "=r"(a) : "l"(p));
  return a;
}
__device__ __forceinline__ void cp16(uint32_t dst, const void* src) {
  asm volatile("cp.async.cg.shared.global [%0], [%1], 16;\n" ::"r"(dst), "l"(src));
}
__device__ __forceinline__ void ldm_x4(uint32_t a, uint32_t* r) {
  asm volatile("ldmatrix.sync.aligned.m8n8.x4.shared.b16 {%0,%1,%2,%3}, [%4];"
               : "=r"(r[0]), "=r"(r[1]), "=r"(r[2]), "=r"(r[3]) : "r"(a));
}
__device__ __forceinline__ void ldm_x2(uint32_t a, uint32_t* r) {
  asm volatile("ldmatrix.sync.aligned.m8n8.x2.shared.b16 {%0,%1}, [%2];"
               : "=r"(r[0]), "=r"(r[1]) : "r"(a));
}
__device__ __forceinline__ void mma16816(float* c, const uint32_t* a,
                                         const uint32_t* b) {
  asm volatile(
      "mma.sync.aligned.m16n8k16.row.col.f32.bf16.bf16.f32 "
      "{%0,%1,%2,%3}, {%4,%5,%6,%7}, {%8,%9}, {%0,%1,%2,%3};"
      : "+f"(c[0]), "+f"(c[1]), "+f"(c[2]), "+f"(c[3])
      : "r"(a[0]), "r"(a[1]), "r"(a[2]), "r"(a[3]), "r"(b[0]), "r"(b[1]));
}

// ------------------------- embedding gather (split bf16, row-major) ----------
__global__ void embed_kernel(const int* __restrict__ tok,
                             const float* __restrict__ embW) {
  int idx = blockIdx.x * 256 + threadIdx.x;
  if (idx >= M_ROWS * NHID) return;
  int m = idx >> 9;
  int k = idx & 511;
  float v = embW[(size_t)tok[m] * NHID + k];
  __nv_bfloat16 h = __float2bfloat16(v);
  g_Ehi[idx] = h;
  g_Elo[idx] = __float2bfloat16(v - __bfloat162float(h));
}

// ------------------------- weight split conversions --------------------------
__global__ void convW0_kernel(const float* __restrict__ fcW) {
  int i = blockIdx.x * 256 + threadIdx.x;
  if (i >= 2048 * NHID) return;
  int n = i >> 9, k = i & 511;
  float x = fcW[(size_t)n * 1024 + k];
  __nv_bfloat16 h = __float2bfloat16(x);
  g_W0hi[i] = h;
  g_W0lo[i] = __float2bfloat16(x - __bfloat162float(h));
}

__global__ void convB_kernel(const float* __restrict__ W) {
  int i = blockIdx.x * 256 + threadIdx.x;
  if (i >= NVOC * NHID) return;
  float x = W[i];
  __nv_bfloat16 h = __float2bfloat16(x);
  g_Bhi[i] = h;
  g_Blo[i] = __float2bfloat16(x - __bfloat162float(h));
}

// ------------------------- HMMA GEMM (decoder + gemm0) -----------------------
#define STG 32768                       /* per-stage bytes: A 16K + B 16K */
#define SO_BUF 1024
#define DEC_SMEM (1024 + 3 * STG)       /* 99328 */

__device__ __forceinline__ void dec_load(uint32_t sb, int s, int kt,
                                         int m0, int n0, int tid,
                                         const __nv_bfloat16* Ahi,
                                         const __nv_bfloat16* Alo,
                                         const __nv_bfloat16* Bhi,
                                         const __nv_bfloat16* Blo) {
  const int k0 = kt * 32;
  const uint32_t base = sb + SO_BUF + (uint32_t)s * STG;
#pragma unroll
  for (int i = tid; i < 1024; i += 256) {
    int row = i >> 3, c = i & 7;
    uint32_t phys = base + row * 128 + ((c ^ (row & 7)) << 4);
    size_t goff = (size_t)k0 + (c & 3) * 8;
    const __nv_bfloat16* asrc =
        (c < 4 ? Ahi : Alo) + (size_t)(m0 + row) * NHID + goff;
    cp16(phys, asrc);
    const __nv_bfloat16* bsrc =
        (c < 4 ? Bhi : Blo) + (size_t)(n0 + row) * NHID + goff;
    cp16(phys + 16384, bsrc);
  }
  asm volatile("cp.async.commit_group;\n" ::: "memory");
}

template <bool TRANSC>
__global__ void __launch_bounds__(256, 2)
mma_gemm(const __nv_bfloat16* __restrict__ Ahi,
         const __nv_bfloat16* __restrict__ Alo,
         const __nv_bfloat16* __restrict__ Bhi,
         const __nv_bfloat16* __restrict__ Blo,
         const float* __restrict__ bias, float* __restrict__ C, int ldc) {
  extern __shared__ char smem[];
  uint32_t sb = smem_u32(smem);
  const int tid = threadIdx.x;
  const int wid = tid >> 5;
  const int lane = tid & 31;
  const int m0 = blockIdx.x * 128;
  const int n0 = blockIdx.y * 128;
  const int wm = (wid >> 2) * 64;
  const int wn = (wid & 3) * 32;

  if (tid < 128) ((float*)smem)[tid] = bias[n0 + tid];

  float acc[4][4][4];
#pragma unroll
  for (int i = 0; i < 4; i++)
#pragma unroll
    for (int j = 0; j < 4; j++)
#pragma unroll
      for (int v = 0; v < 4; v++) acc[i][j][v] = 0.f;

  dec_load(sb, 0, 0, m0, n0, tid, Ahi, Alo, Bhi, Blo);
  dec_load(sb, 1, 1, m0, n0, tid, Ahi, Alo, Bhi, Blo);

  const int arow = lane & 15;
  const int ahalf = lane >> 4;
  const int aswz = arow & 7;
  const int brow4 = lane & 7;
  const int bgrp = lane >> 3;
  const int brow_off = (bgrp >> 1) * 8;
  const int bkhalf = bgrp & 1;

  int s_cur = 0, s_nxt = 2;
#pragma unroll 1
  for (int kt = 0; kt < 16; ++kt) {
    if (kt == 15)
      asm volatile("cp.async.wait_group 0;\n" ::: "memory");
    else
      asm volatile("cp.async.wait_group 1;\n" ::: "memory");
    __syncthreads();

    if (kt + 2 < 16)
      dec_load(sb, s_nxt, kt + 2, m0, n0, tid, Ahi, Alo, Bhi, Blo);

    const uint32_t abase = sb + SO_BUF + (uint32_t)s_cur * STG;
    const uint32_t bbase = abase + 16384;

#pragma unroll
    for (int ks = 0; ks < 2; ++ks) {
      uint32_t ah[4][4], al[4][4];
      const int achunk = (ks * 2 + ahalf) ^ aswz;
#pragma unroll
      for (int mf = 0; mf < 4; ++mf) {
        uint32_t addr = abase + (uint32_t)(wm + mf * 16 + arow) * 128 +
                        (achunk << 4);
        ldm_x4(addr, ah[mf]);
        ldm_x4(addr ^ 64, al[mf]);
      }
      const int bchunk = (ks * 2 + bkhalf) ^ brow4;
#pragma unroll
      for (int nfp = 0; nfp < 2; ++nfp) {
        uint32_t bh[4], bl[4];
        uint32_t addr = bbase +
                        (uint32_t)(wn + nfp * 16 + brow_off + brow4) * 128 +
                        (bchunk << 4);
        ldm_x4(addr, bh);
        ldm_x4(addr ^ 64, bl);
        const int ne = nfp * 2, no = nfp * 2 + 1;
#pragma unroll
        for (int mf = 0; mf < 4; ++mf) {
          mma16816(acc[mf][ne], ah[mf], bh);
          mma16816(acc[mf][no], ah[mf], bh + 2);
        }
#pragma unroll
        for (int mf = 0; mf < 4; ++mf) {
          mma16816(acc[mf][ne], ah[mf], bl);
          mma16816(acc[mf][no], ah[mf], bl + 2);
        }
#pragma unroll
        for (int mf = 0; mf < 4; ++mf) {
          mma16816(acc[mf][ne], al[mf], bh);
          mma16816(acc[mf][no], al[mf], bh + 2);
        }
      }
    }
    s_cur = s_cur == 2 ? 0 : s_cur + 1;
    s_nxt = s_nxt == 2 ? 0 : s_nxt + 1;
  }

  const float* bsm = (const float*)smem;
  const int rl = lane >> 2, cl = (lane & 3) * 2;
  if (!TRANSC) {
#pragma unroll
    for (int mf = 0; mf < 4; ++mf) {
      int r = m0 + wm + mf * 16 + rl;
#pragma unroll
      for (int nf = 0; nf < 4; ++nf) {
        int ci = wn + nf * 8 + cl;
        float b0 = bsm[ci], b1 = bsm[ci + 1];
        float2 v0 = make_float2(acc[mf][nf][0] + b0, acc[mf][nf][1] + b1);
        float2 v1 = make_float2(acc[mf][nf][2] + b0, acc[mf][nf][3] + b1);
        *(float2*)(C + (size_t)r * ldc + n0 + ci) = v0;
        *(float2*)(C + (size_t)(r + 8) * ldc + n0 + ci) = v1;
      }
    }
  } else {
#pragma unroll
    for (int mf = 0; mf < 4; ++mf) {
      int r = m0 + wm + mf * 16 + rl;
#pragma unroll
      for (int nf = 0; nf < 4; ++nf) {
        int ci = wn + nf * 8 + cl;
        float b0 = bsm[ci], b1 = bsm[ci + 1];
        C[(size_t)(n0 + ci) * ldc + r] = acc[mf][nf][0] + b0;
        C[(size_t)(n0 + ci + 1) * ldc + r] = acc[mf][nf][1] + b1;
        C[(size_t)(n0 + ci) * ldc + r + 8] = acc[mf][nf][2] + b0;
        C[(size_t)(n0 + ci + 1) * ldc + r + 8] = acc[mf][nf][3] + b1;
      }
    }
  }
}

// ------------------------- HMMA persistent LSTM ------------------------------
// smem (bytes): packed 128B-block layouts, overlays noted
#define SO_W0 0                 /* 16 rows x 2048B = 32KB */
#define SO_W1 32768             /* 16 rows x 4096B = 64KB */
#define SO_H0 98304             /* 32 rows x 2048B = 64KB ; a_sm overlays */
#define SO_H1 163840            /* 64KB ; ps overlays */
#define SO_ASM SO_H0            /* 32*32 f32 = 4KB (after part1 done) */
#define SO_PS  SO_H1            /* 8*32*32 f32 = 32KB (after part2 done) */
#define SO_B1S 229376           /* 16 f32, persistent */
#define LSTM_SMEM 229440

__device__ __forceinline__ void gridbar() {
  __threadfence();
  __syncthreads();
  if (threadIdx.x == 0) {
    unsigned e = *(volatile unsigned*)&g_epoch;
    __threadfence();
    unsigned prev = atomicAdd(&g_count, 1u);
    if (prev == (unsigned)(LSTM_GRID - 1)) {
      atomicExch(&g_count, 0u);
      __threadfence();
      atomicAdd(&g_epoch, 1u);
    } else {
      while (*(volatile unsigned*)&g_epoch == e) __nanosleep(64);
    }
    __threadfence();
  }
  __syncthreads();
}

// cp.async 64KB h matrix (plain 128B blocks) into swizzled smem buffer
__device__ __forceinline__ void stage_cp(uint32_t dstbase,
                                         const unsigned char* __restrict__ src) {
  const int tid = threadIdx.x;
#pragma unroll
  for (int it = 0; it < 16; ++it) {
    int i = tid + it * 256;
    int row = i >> 7, t = i & 127, j = t >> 3, c = t & 7;
    uint32_t dst = dstbase + (uint32_t)row * 2048 + j * 128 +
                   ((c ^ (row & 7)) << 4);
    cp16(dst, src + (size_t)i * 16);
  }
  asm volatile("cp.async.commit_group;\n" ::: "memory");
}

__device__ __forceinline__ float sigm(float x) { return 1.f / (1.f + __expf(-x)); }

__global__ void __launch_bounds__(256, 1)
lstm_kernel(const float* __restrict__ fcW, const float* __restrict__ fcb,
            float* __restrict__ out) {
  extern __shared__ char smem[];
  uint32_t sb = smem_u32(smem);
  float* ps = (float*)(smem + SO_PS);
  float* a_sm = (float*)(smem + SO_ASM);
  float* b1s = (float*)(smem + SO_B1S);

  const int tid = threadIdx.x;
  const int w = tid >> 5;
  const int lane = tid & 31;
  const int cta = blockIdx.x;

  // ---- load + split weight slices into packed smem layout (once) ----
  // local row r: unit j=r>>2, gate gg=r&3 -> global gate row gr = cta*4 + j + gg*512
  for (int i = tid; i < 16 * 512; i += 256) {
    int r = i >> 9, k = i & 511;
    int gr = cta * 4 + (r >> 2) + (r & 3) * 512;
    float v = fcW[(size_t)gr * 1024 + 512 + k];           // layer0 h-part
    __nv_bfloat16 h = __float2bfloat16(v);
    uint32_t off = (uint32_t)r * 2048 + (k >> 5) * 128 +
                   (((((k & 31) >> 3)) ^ (r & 7)) << 4) + (k & 7) * 2;
    *(__nv_bfloat16*)(smem + SO_W0 + off) = h;
    *(__nv_bfloat16*)(smem + SO_W0 + (off ^ 64)) =
        __float2bfloat16(v - __bfloat162float(h));
  }
  for (int i = tid; i < 16 * 1024; i += 256) {
    int r = i >> 10, k = i & 1023;
    int gr = cta * 4 + (r >> 2) + (r & 3) * 512;
    float v = fcW[(size_t)2048 * 1024 + (size_t)gr * 1024 + k];  // layer1 full
    __nv_bfloat16 h = __float2bfloat16(v);
    uint32_t off = (uint32_t)r * 4096 + (k >> 5) * 128 +
                   (((((k & 31) >> 3)) ^ (r & 7)) << 4) + (k & 7) * 2;
    *(__nv_bfloat16*)(smem + SO_W1 + off) = h;
    *(__nv_bfloat16*)(smem + SO_W1 + (off ^ 64)) =
        __float2bfloat16(v - __bfloat162float(h));
  }
  if (tid < 16)
    b1s[tid] = fcb[2048 + cta * 4 + (tid >> 2) + (tid & 3) * 512];

  // ---- zero initial hidden state (both parities) ----
  {
    int g = cta * 256 + tid;
    uint4 z = make_uint4(0, 0, 0, 0);
    if (g < 2 * BATCH * 2048 / 16) {
      ((uint4*)g_H0s)[g] = z;
      ((uint4*)g_H1s)[g] = z;
    }
  }
  gridbar();

  float c0r = 0.f, c1r = 0.f;  // warps 0..3: c0 of unit U; warps 4..7: c1
  const int U = cta * 4 + (w & 3);
  float* hid = out + HID_OFF;

  const int arow = lane & 15, ahalf = lane >> 4;
  const int brow = lane & 7, bhalf = (lane >> 3) & 1;
  const int rl = lane >> 2, cl = (lane & 3) * 2;

  // phase p: layer0 at t=p (p<128), layer1 at t=p-1 (p>=1). 129 phases.
#pragma unroll 1
  for (int p = 0; p <= SEQ; ++p) {
    const int wp = p & 1;

    // both h inputs are ready at phase start: issue both async stages now
    stage_cp(sb + SO_H0, g_H0s[wp ^ 1]);
    stage_cp(sb + SO_H1, g_H1s[wp ^ 1]);

    // prefetch layer0 x-gates (hidden behind staging)
    float xg[4] = {0.f, 0.f, 0.f, 0.f};
    if (w < 4 && p < SEQ) {
#pragma unroll
      for (int g = 0; g < 4; ++g)
        xg[g] = g_g0xT[(size_t)(U + g * 512) * M_ROWS + p * 32 + lane];
    }

    float acc0[2][2][4], acc1[2][2][4];
#pragma unroll
    for (int i = 0; i < 2; i++)
#pragma unroll
      for (int j = 0; j < 2; j++)
#pragma unroll
        for (int v = 0; v < 4; v++) { acc0[i][j][v] = 0.f; acc1[i][j][v] = 0.f; }

    // ---- part 1: h0(prev) -> L0 gates + L1 chunk0 (shared A frags) ----
    asm volatile("cp.async.wait_group 1;\n" ::: "memory");
    __syncthreads();
#pragma unroll
    for (int kt = 0; kt < 4; ++kt) {
      const int j = (w * 4 + kt) >> 1;
      const int cb = (kt & 1) * 2;
      uint32_t ah[2][4], al[2][4], b0h[2][2], b0l[2][2], b1h[2][2], b1l[2][2];
#pragma unroll
      for (int mf = 0; mf < 2; ++mf) {
        uint32_t addr = sb + SO_H0 + (uint32_t)(mf * 16 + arow) * 2048 +
                        j * 128 + (((cb + ahalf) ^ (arow & 7)) << 4);
        ldm_x4(addr, ah[mf]);
        ldm_x4(addr ^ 64, al[mf]);
      }
#pragma unroll
      for (int nf = 0; nf < 2; ++nf) {
        uint32_t swz = ((cb + bhalf) ^ brow) << 4;
        uint32_t a0 = sb + SO_W0 + (uint32_t)(nf * 8 + brow) * 2048 + j * 128 + swz;
        ldm_x2(a0, b0h[nf]);
        ldm_x2(a0 ^ 64, b0l[nf]);
        uint32_t a1 = sb + SO_W1 + (uint32_t)(nf * 8 + brow) * 4096 + j * 128 + swz;
        ldm_x2(a1, b1h[nf]);
        ldm_x2(a1 ^ 64, b1l[nf]);
      }
#pragma unroll
      for (int mf = 0; mf < 2; ++mf)
#pragma unroll
        for (int nf = 0; nf < 2; ++nf) {
          mma16816(acc0[mf][nf], ah[mf], b0h[nf]);
          mma16816(acc1[mf][nf], ah[mf], b1h[nf]);
        }
#pragma unroll
      for (int mf = 0; mf < 2; ++mf)
#pragma unroll
        for (int nf = 0; nf < 2; ++nf) {
          mma16816(acc0[mf][nf], ah[mf], b0l[nf]);
          mma16816(acc1[mf][nf], ah[mf], b1l[nf]);
        }
#pragma unroll
      for (int mf = 0; mf < 2; ++mf)
#pragma unroll
        for (int nf = 0; nf < 2; ++nf) {
          mma16816(acc0[mf][nf], al[mf], b0h[nf]);
          mma16816(acc1[mf][nf], al[mf], b1h[nf]);
        }
    }

    // ---- part 2: h1(prev) -> L1 chunk1 (already staged) ----
    asm volatile("cp.async.wait_group 0;\n" ::: "memory");
    __syncthreads();
#pragma unroll
    for (int kt = 0; kt < 4; ++kt) {
      const int j = (w * 4 + kt) >> 1;
      const int cb = (kt & 1) * 2;
      uint32_t ah[2][4], al[2][4], b1h[2][2], b1l[2][2];
#pragma unroll
      for (int mf = 0; mf < 2; ++mf) {
        uint32_t addr = sb + SO_H1 + (uint32_t)(mf * 16 + arow) * 2048 +
                        j * 128 + (((cb + ahalf) ^ (arow & 7)) << 4);
        ldm_x4(addr, ah[mf]);
        ldm_x4(addr ^ 64, al[mf]);
      }
#pragma unroll
      for (int nf = 0; nf < 2; ++nf) {
        uint32_t swz = ((cb + bhalf) ^ brow) << 4;
        uint32_t a1 = sb + SO_W1 + (uint32_t)(nf * 8 + brow) * 4096 +
                      (16 + j) * 128 + swz;
        ldm_x2(a1, b1h[nf]);
        ldm_x2(a1 ^ 64, b1l[nf]);
      }
#pragma unroll
      for (int mf = 0; mf < 2; ++mf)
#pragma unroll
        for (int nf = 0; nf < 2; ++nf) mma16816(acc1[mf][nf], ah[mf], b1h[nf]);
#pragma unroll
      for (int mf = 0; mf < 2; ++mf)
#pragma unroll
        for (int nf = 0; nf < 2; ++nf) mma16816(acc1[mf][nf], ah[mf], b1l[nf]);
#pragma unroll
      for (int mf = 0; mf < 2; ++mf)
#pragma unroll
        for (int nf = 0; nf < 2; ++nf) mma16816(acc1[mf][nf], al[mf], b1h[nf]);
    }
    __syncthreads();   // all H1 reads done before ps overlays it

    // ---- store partials: ps[warp][n][b], n<16 = L0, n>=16 = L1 ----
#pragma unroll
    for (int mf = 0; mf < 2; ++mf)
#pragma unroll
      for (int nf = 0; nf < 2; ++nf)
#pragma unroll
        for (int v = 0; v < 4; ++v) {
          int b = mf * 16 + rl + ((v & 2) ? 8 : 0);
          int n = nf * 8 + cl + (v & 1);
          ps[(w * 32 + n) * 32 + b] = acc0[mf][nf][v];
          ps[(w * 32 + 16 + n) * 32 + b] = acc1[mf][nf][v];
        }
    __syncthreads();

    // ---- reduce 8 partials -> a_sm[n][b] (overlays H0; part1 done) ----
#pragma unroll
    for (int q = 0; q < 4; ++q) {
      int o = tid + q * 256;
      int n = o >> 5, b = o & 31;
      float s = 0.f;
#pragma unroll
      for (int ww = 0; ww < 8; ++ww) s += ps[(ww * 32 + n) * 32 + b];
      a_sm[n * 32 + b] = s;
    }
    __syncthreads();

    // ---- activations + state update (h written as split-bf16) ----
    if (w < 4) {
      if (p < SEQ) {
        float a[4];
#pragma unroll
        for (int g = 0; g < 4; ++g)
          a[g] = a_sm[(w * 4 + g) * 32 + lane] + xg[g];
        float ig = sigm(a[0]), fg = sigm(a[1]), og = sigm(a[2]);
        float bg = tanhf(a[3]);
        c0r = fg * c0r + ig * bg;
        float h0v = og * tanhf(c0r);
        __nv_bfloat16 hh = __float2bfloat16(h0v);
        __nv_bfloat16 ll = __float2bfloat16(h0v - __bfloat162float(hh));
        unsigned char* d = g_H0s[wp] + lane * 2048 + (U >> 5) * 128 + (U & 31) * 2;
        *(__nv_bfloat16*)d = hh;
        *(__nv_bfloat16*)(d + 64) = ll;
        if (p == SEQ - 1) hid[lane * 512 + U] = h0v;
      }
    } else {
      if (p >= 1) {
        float a[4];
#pragma unroll
        for (int g = 0; g < 4; ++g)
          a[g] = a_sm[(16 + (w - 4) * 4 + g) * 32 + lane] + b1s[(w - 4) * 4 + g];
        float ig = sigm(a[0]), fg = sigm(a[1]), og = sigm(a[2]);
        float bg = tanhf(a[3]);
        c1r = fg * c1r + ig * bg;
        float h1v = og * tanhf(c1r);
        __nv_bfloat16 hh = __float2bfloat16(h1v);
        __nv_bfloat16 ll = __float2bfloat16(h1v - __bfloat162float(hh));
        unsigned char* d = g_H1s[wp] + lane * 2048 + (U >> 5) * 128 + (U & 31) * 2;
        *(__nv_bfloat16*)d = hh;
        *(__nv_bfloat16*)(d + 64) = ll;
        // fused decoder A operand (row-major [m][k])
        size_t o = (size_t)((p - 1) * 32 + lane) * NHID + U;
        g_Ahi[o] = hh;
        g_Alo[o] = ll;
        if (p == SEQ) hid[16384 + lane * 512 + U] = h1v;
      }
    }
    gridbar();
  }
}

// ------------------------- launch ------------------------------------------
extern "C" void kernel_launch(void* const* d_in, const int* in_sizes, int n_in,
                              void* d_out, int out_size) {
  const int* tok = (const int*)d_in[0];
  const float* embW = (const float*)d_in[1];
  const float* fcW = (const float*)d_in[2];
  const float* fcb = (const float*)d_in[3];
  const float* decW = (const float*)d_in[4];
  const float* decb = (const float*)d_in[5];
  float* out = (float*)d_out;

  void *p_g0xT = 0, *p_Ehi = 0, *p_Elo = 0, *p_W0hi = 0, *p_W0lo = 0;
  void *p_Ahi = 0, *p_Alo = 0, *p_Bhi = 0, *p_Blo = 0;
  cudaGetSymbolAddress(&p_g0xT, g_g0xT);
  cudaGetSymbolAddress(&p_Ehi, g_Ehi);
  cudaGetSymbolAddress(&p_Elo, g_Elo);
  cudaGetSymbolAddress(&p_W0hi, g_W0hi);
  cudaGetSymbolAddress(&p_W0lo, g_W0lo);
  cudaGetSymbolAddress(&p_Ahi, g_Ahi);
  cudaGetSymbolAddress(&p_Alo, g_Alo);
  cudaGetSymbolAddress(&p_Bhi, g_Bhi);
  cudaGetSymbolAddress(&p_Blo, g_Blo);

  cudaFuncSetAttribute(mma_gemm<false>,
                       cudaFuncAttributeMaxDynamicSharedMemorySize, DEC_SMEM);
  cudaFuncSetAttribute(mma_gemm<true>,
                       cudaFuncAttributeMaxDynamicSharedMemorySize, DEC_SMEM);
  cudaFuncSetAttribute(lstm_kernel,
                       cudaFuncAttributeMaxDynamicSharedMemorySize, LSTM_SMEM);

  // 1) embedding gather -> split bf16 row-major
  embed_kernel<<<(M_ROWS * NHID + 255) / 256, 256>>>(tok, embW);

  // 2) weight splits
  convW0_kernel<<<(2048 * NHID + 255) / 256, 256>>>(fcW);
  convB_kernel<<<(NVOC * NHID + 255) / 256, 256>>>(decW);

  // 3) layer-0 input projection (HMMA): g0xT[n][m] = emb . W0^T + b0
  mma_gemm<true><<<dim3(M_ROWS / 128, 2048 / 128), 256, DEC_SMEM>>>(
      (const __nv_bfloat16*)p_Ehi, (const __nv_bfloat16*)p_Elo,
      (const __nv_bfloat16*)p_W0hi, (const __nv_bfloat16*)p_W0lo,
      fcb, (float*)p_g0xT, M_ROWS);

  // 4) persistent HMMA LSTM recurrence (split-bf16 h state, async staging)
  lstm_kernel<<<LSTM_GRID, 256, LSTM_SMEM>>>(fcW, fcb, out);

  // 5) HMMA decoder GEMM
  mma_gemm<false><<<dim3(M_ROWS / 128, NVOC / 128), 256, DEC_SMEM>>>(
      (const __nv_bfloat16*)p_Ahi, (const __nv_bfloat16*)p_Alo,
      (const __nv_bfloat16*)p_Bhi, (const __nv_bfloat16*)p_Blo,
      decb, out, NVOC);
}